// round 8
// baseline (speedup 1.0000x reference)
#include <cuda_runtime.h>
#include <cuda_bf16.h>
#include <cstdint>

// ---------------------------------------------------------------------------
// Problem constants
// ---------------------------------------------------------------------------
#define N_NODES   8192
#define F_DIM     1024
#define O_DIM     1024
#define K_DIM     2048          // 2*F
#define NUM_NEIGH 10

// GEMM tiling (mma.sync path; tcgen05 unavailable: toolchain emits compute_103
// PTX which rejects sm_103a-only instructions)
#define BM        128
#define BN        128
#define BK        32            // k elements per stage (32 bf16 = 64B rows)
#define STAGES    4
#define CHUNKS    192           // 3 split-segments * (2048/32)
#define STAGE_BYTES 16384       // 8KB A + 8KB B
#define SMEM_NEED  (STAGES * STAGE_BYTES)

// ---------------------------------------------------------------------------
// Split operand scratch (device globals: allowed under allocation guards)
// ---------------------------------------------------------------------------
__device__ __nv_bfloat16 g_Ahi[(size_t)N_NODES * K_DIM];   // 32 MB
__device__ __nv_bfloat16 g_Alo[(size_t)N_NODES * K_DIM];   // 32 MB
__device__ __nv_bfloat16 g_Bhi[(size_t)O_DIM   * K_DIM];   // 4 MB  (W^T hi, K-major)
__device__ __nv_bfloat16 g_Blo[(size_t)O_DIM   * K_DIM];   // 4 MB  (W^T lo, K-major)

// ---------------------------------------------------------------------------
// PTX helpers
// ---------------------------------------------------------------------------
__device__ __forceinline__ uint32_t smem_u32(const void* p) {
    uint32_t a;
    asm("{ .reg .u64 t; cvta.to.shared.u64 t, %1; cvt.u32.u64 %0, t; }" : "=r"(a) : "l"(p));
    return a;
}
__device__ __forceinline__ void cp_async16(uint32_t dst, const void* src) {
    asm volatile("cp.async.cg.shared.global [%0], [%1], 16;" :: "r"(dst), "l"(src) : "memory");
}
__device__ __forceinline__ void cp_commit() {
    asm volatile("cp.async.commit_group;" ::: "memory");
}
template <int N>
__device__ __forceinline__ void cp_wait() {
    asm volatile("cp.async.wait_group %0;" :: "n"(N) : "memory");
}
__device__ __forceinline__ void ldsm4(uint32_t* r, uint32_t addr) {
    asm volatile("ldmatrix.sync.aligned.m8n8.x4.shared.b16 {%0,%1,%2,%3}, [%4];"
                 : "=r"(r[0]), "=r"(r[1]), "=r"(r[2]), "=r"(r[3]) : "r"(addr));
}
__device__ __forceinline__ void mma_bf16(float* c, const uint32_t* a, uint32_t b0, uint32_t b1) {
    asm volatile("mma.sync.aligned.m16n8k16.row.col.f32.bf16.bf16.f32 "
                 "{%0,%1,%2,%3}, {%4,%5,%6,%7}, {%8,%9}, {%0,%1,%2,%3};"
                 : "+f"(c[0]), "+f"(c[1]), "+f"(c[2]), "+f"(c[3])
                 : "r"(a[0]), "r"(a[1]), "r"(a[2]), "r"(a[3]), "r"(b0), "r"(b1));
}

// ---------------------------------------------------------------------------
// hi/lo bf16 split
// ---------------------------------------------------------------------------
__device__ __forceinline__ void split2(float v, unsigned short& h, unsigned short& l) {
    __nv_bfloat16 hb = __float2bfloat16_rn(v);
    __nv_bfloat16 lb = __float2bfloat16_rn(v - __bfloat162float(hb));
    h = __bfloat16_as_ushort(hb);
    l = __bfloat16_as_ushort(lb);
}

// ---------------------------------------------------------------------------
// Kernel 1: split X -> Ahi/Alo[:, 0:1024]
// ---------------------------------------------------------------------------
__global__ void __launch_bounds__(256)
convertX_kernel(const float* __restrict__ X)
{
    const int t = blockIdx.x * 256 + threadIdx.x;
    const int m = t >> 8;
    const int f = (t & 255) << 2;
    const float4 v = *reinterpret_cast<const float4*>(X + (size_t)m * F_DIM + f);
    ushort4 hv, lv;
    split2(v.x, hv.x, lv.x); split2(v.y, hv.y, lv.y);
    split2(v.z, hv.z, lv.z); split2(v.w, hv.w, lv.w);
    *reinterpret_cast<ushort4*>(&g_Ahi[(size_t)m * K_DIM + f]) = hv;
    *reinterpret_cast<ushort4*>(&g_Alo[(size_t)m * K_DIM + f]) = lv;
}

// ---------------------------------------------------------------------------
// Kernel 2: aggregate + split -> Ahi/Alo[:, 1024:2048]
// ---------------------------------------------------------------------------
__global__ void __launch_bounds__(256)
aggregate_kernel(const float* __restrict__ X, const int* __restrict__ idx)
{
    const int n  = blockIdx.x;
    const int f4 = threadIdx.x;
    const int* row_idx = idx + n * NUM_NEIGH;
    float4 acc = make_float4(0.f, 0.f, 0.f, 0.f);
#pragma unroll
    for (int j = 0; j < NUM_NEIGH; ++j) {
        const int nb = row_idx[j];
        const float4 v = *reinterpret_cast<const float4*>(X + (size_t)nb * F_DIM + f4 * 4);
        acc.x += v.x; acc.y += v.y; acc.z += v.z; acc.w += v.w;
    }
    const float s = 1.0f / NUM_NEIGH;
    acc.x *= s; acc.y *= s; acc.z *= s; acc.w *= s;
    ushort4 hv, lv;
    split2(acc.x, hv.x, lv.x); split2(acc.y, hv.y, lv.y);
    split2(acc.z, hv.z, lv.z); split2(acc.w, hv.w, lv.w);
    const size_t o = (size_t)n * K_DIM + F_DIM + f4 * 4;
    *reinterpret_cast<ushort4*>(&g_Ahi[o]) = hv;
    *reinterpret_cast<ushort4*>(&g_Alo[o]) = lv;
}

// ---------------------------------------------------------------------------
// Kernel 3: transpose + split W[2048,1024] -> Bhi/Blo[1024,2048] (K-major)
// ---------------------------------------------------------------------------
__global__ void __launch_bounds__(256)
convertW_kernel(const float* __restrict__ W)
{
    __shared__ float tile[32][33];
    const int n0 = blockIdx.x * 32;
    const int k0 = blockIdx.y * 32;
    const int tx = threadIdx.x & 31;
    const int ty = threadIdx.x >> 5;          // 0..7
    for (int i = ty; i < 32; i += 8)
        tile[i][tx] = W[(size_t)(k0 + i) * O_DIM + n0 + tx];
    __syncthreads();
    for (int i = ty; i < 32; i += 8) {
        const float v = tile[tx][i];          // W[k0+tx][n0+i]
        unsigned short h, l;
        split2(v, h, l);
        const size_t o = (size_t)(n0 + i) * K_DIM + k0 + tx;
        g_Bhi[o] = __ushort_as_bfloat16(h);
        g_Blo[o] = __ushort_as_bfloat16(l);
    }
}

// ---------------------------------------------------------------------------
// Kernel 4: mma.sync bf16 GEMM over K' = 3*2048
//   out = Ahi@Bhi' + Ahi@Blo' + Alo@Bhi' + bias
// CTA 128x128, 4 warps (2x2) each 64x64, BK=32, 4-stage cp.async pipeline.
// ONE __syncthreads per chunk (cutlass multistage order): wait oldest group ->
// barrier -> issue next stage loads -> compute. 16B-chunk swizzle keeps LDSM
// conflict-free.
// ---------------------------------------------------------------------------
__global__ void __launch_bounds__(128, 3)
gemm_kernel(const float* __restrict__ bias, float* __restrict__ out)
{
    extern __shared__ char smem_raw[];
    const uint32_t smem = smem_u32(smem_raw);

    const int tid  = threadIdx.x;
    const int lane = tid & 31;
    const int wid  = tid >> 5;
    const int m0 = blockIdx.y * BM;
    const int n0 = blockIdx.x * BN;
    const int wm = (wid >> 1) * 64;       // warp row offset
    const int wn = (wid & 1) * 64;        // warp col offset

    const __nv_bfloat16* const Aseg[3] = { g_Ahi, g_Ahi, g_Alo };
    const __nv_bfloat16* const Bseg[3] = { g_Bhi, g_Blo, g_Bhi };

    // per-thread cp.async mapping: row = tid, 4 x 16B chunks, swizzled
    const int swz = (tid >> 1) & 3;

    auto load_stage = [&](int s, int it) {
        const int seg = it >> 6;                  // 0..2
        const int kk  = (it & 63) << 5;           // k offset in elements
        const char* srcA = (const char*)(Aseg[seg] + (size_t)(m0 + tid) * K_DIM + kk);
        const char* srcB = (const char*)(Bseg[seg] + (size_t)(n0 + tid) * K_DIM + kk);
        const uint32_t dA = smem + s * STAGE_BYTES + tid * 64;
        const uint32_t dB = dA + 8192;
#pragma unroll
        for (int c = 0; c < 4; ++c) {
            cp_async16(dA + ((c ^ swz) << 4), srcA + (c << 4));
            cp_async16(dB + ((c ^ swz) << 4), srcB + (c << 4));
        }
    };

    float acc[4][8][4];
#pragma unroll
    for (int i = 0; i < 4; ++i)
#pragma unroll
        for (int j = 0; j < 8; ++j)
#pragma unroll
            for (int v = 0; v < 4; ++v) acc[i][j][v] = 0.f;

    // prologue: fill STAGES-1 stages
#pragma unroll
    for (int s = 0; s < STAGES - 1; ++s) {
        load_stage(s, s);
        cp_commit();
    }

    // ldmatrix lane addressing: precompute per-warp row byte-offsets + row swizzle
    const int lrow = lane & 15;
    const int lkc  = lane >> 4;               // 0/1: which 16B k-chunk pair
    uint32_t aoff[4], boff[4];                // row*64 for the 4 m/n subtiles
    int arsw[4], brsw[4];                     // ((row>>1)&3) per subtile
#pragma unroll
    for (int t = 0; t < 4; ++t) {
        const int ra = wm + t * 16 + lrow;
        const int rb = wn + t * 16 + lrow;
        aoff[t] = ra * 64; arsw[t] = (ra >> 1) & 3;
        boff[t] = rb * 64; brsw[t] = (rb >> 1) & 3;
    }

    for (int it = 0; it < CHUNKS; ++it) {
        // oldest in-flight group (this iteration's stage) has arrived
        cp_wait<STAGES - 2>();
        __syncthreads();   // all warps done reading the stage we're about to overwrite

        // issue next stage's loads FIRST so they overlap the MMAs below
        if (it + STAGES - 1 < CHUNKS)
            load_stage((it + STAGES - 1) & (STAGES - 1), it + STAGES - 1);
        cp_commit();       // unconditional: keeps group count aligned

        const uint32_t sA = smem + (it & (STAGES - 1)) * STAGE_BYTES;
        const uint32_t sB = sA + 8192;

#pragma unroll
        for (int k16 = 0; k16 < 2; ++k16) {
            uint32_t afr[4][4], bfr[4][4];
            const int kc = k16 * 2 + lkc;
#pragma unroll
            for (int tm = 0; tm < 4; ++tm)
                ldsm4(afr[tm], sA + aoff[tm] + ((kc ^ arsw[tm]) << 4));
#pragma unroll
            for (int tn2 = 0; tn2 < 4; ++tn2)
                ldsm4(bfr[tn2], sB + boff[tn2] + ((kc ^ brsw[tn2]) << 4));
#pragma unroll
            for (int tm = 0; tm < 4; ++tm)
#pragma unroll
                for (int tn = 0; tn < 8; ++tn)
                    mma_bf16(acc[tm][tn], afr[tm],
                             bfr[tn >> 1][tn & 1], bfr[tn >> 1][(tn & 1) + 2]);
        }
    }

    // ---- epilogue: + bias, direct f32 stores (float2 per fragment row) ----
    const int qn = (lane & 3) * 2;   // n offset within n8 tile
    const int qm = lane >> 2;        // m offset within m16 tile (0..7)
    float2 b2[8];
#pragma unroll
    for (int tn = 0; tn < 8; ++tn) {
        const int n = n0 + wn + tn * 8 + qn;
        b2[tn] = *reinterpret_cast<const float2*>(bias + n);
    }
#pragma unroll
    for (int tm = 0; tm < 4; ++tm) {
        const int m = m0 + wm + tm * 16 + qm;
#pragma unroll
        for (int tn = 0; tn < 8; ++tn) {
            const int n = n0 + wn + tn * 8 + qn;
            float2 lo, hi;
            lo.x = acc[tm][tn][0] + b2[tn].x;
            lo.y = acc[tm][tn][1] + b2[tn].y;
            hi.x = acc[tm][tn][2] + b2[tn].x;
            hi.y = acc[tm][tn][3] + b2[tn].y;
            *reinterpret_cast<float2*>(out + (size_t)m * O_DIM + n)       = lo;
            *reinterpret_cast<float2*>(out + (size_t)(m + 8) * O_DIM + n) = hi;
        }
    }
}

// ---------------------------------------------------------------------------
// Launch: inputs in metadata order: X, A(unused), W, b, sampled_idx
// ---------------------------------------------------------------------------
extern "C" void kernel_launch(void* const* d_in, const int* in_sizes, int n_in,
                              void* d_out, int out_size)
{
    const float* X    = (const float*)d_in[0];
    const float* W    = (const float*)d_in[2];
    const float* bias = (const float*)d_in[3];
    const int*   idx  = (const int*)d_in[4];
    float* out = (float*)d_out;

    cudaFuncSetAttribute(gemm_kernel, cudaFuncAttributeMaxDynamicSharedMemorySize, SMEM_NEED);

    convertX_kernel<<<(N_NODES * F_DIM / 4) / 256, 256>>>(X);
    convertW_kernel<<<dim3(O_DIM / 32, K_DIM / 32), 256>>>(W);
    aggregate_kernel<<<N_NODES, 256>>>(X, idx);

    dim3 grid(O_DIM / BN, N_NODES / BM);   // (8, 64) = 512 CTAs
    gemm_kernel<<<grid, 128, SMEM_NEED>>>(bias, out);
    (void)in_sizes; (void)n_in; (void)out_size;
}

// round 13
// speedup vs baseline: 1.1181x; 1.1181x over previous
#include <cuda_runtime.h>
#include <cuda_bf16.h>
#include <cstdint>

// ---------------------------------------------------------------------------
// Problem constants
// ---------------------------------------------------------------------------
#define N_NODES   8192
#define F_DIM     1024
#define O_DIM     1024
#define K_DIM     2048          // 2*F
#define NUM_NEIGH 10

// GEMM tiling (mma.sync path; tcgen05 unavailable: toolchain emits compute_103
// PTX which rejects sm_103a-only instructions)
#define BM        128
#define BN        128
#define BK        32            // k elements per stage
#define STAGES    4
#define CHUNKS    192           // 3 split-segments * (2048/32)
#define ROW_BYTES 80            // 64B of data + 16B pad: conflict-free LDSM/STS
#define TILE_BYTES (128 * ROW_BYTES)        // 10240
#define STAGE_BYTES (2 * TILE_BYTES)        // 20480 (A + B)
#define SMEM_NEED  (STAGES * STAGE_BYTES)   // 81920
#define NTHREADS  256

// ---------------------------------------------------------------------------
// Split operand scratch (device globals: allowed under allocation guards)
// ---------------------------------------------------------------------------
__device__ __nv_bfloat16 g_Ahi[(size_t)N_NODES * K_DIM];   // 32 MB
__device__ __nv_bfloat16 g_Alo[(size_t)N_NODES * K_DIM];   // 32 MB
__device__ __nv_bfloat16 g_Bhi[(size_t)O_DIM   * K_DIM];   // 4 MB  (W^T hi, K-major)
__device__ __nv_bfloat16 g_Blo[(size_t)O_DIM   * K_DIM];   // 4 MB  (W^T lo, K-major)

// ---------------------------------------------------------------------------
// PTX helpers
// ---------------------------------------------------------------------------
__device__ __forceinline__ uint32_t smem_u32(const void* p) {
    uint32_t a;
    asm("{ .reg .u64 t; cvta.to.shared.u64 t, %1; cvt.u32.u64 %0, t; }" : "=r"(a) : "l"(p));
    return a;
}
__device__ __forceinline__ void cp_async16(uint32_t dst, const void* src) {
    asm volatile("cp.async.cg.shared.global [%0], [%1], 16;" :: "r"(dst), "l"(src) : "memory");
}
__device__ __forceinline__ void cp_commit() {
    asm volatile("cp.async.commit_group;" ::: "memory");
}
template <int N>
__device__ __forceinline__ void cp_wait() {
    asm volatile("cp.async.wait_group %0;" :: "n"(N) : "memory");
}
__device__ __forceinline__ void ldsm4(uint32_t* r, uint32_t addr) {
    asm volatile("ldmatrix.sync.aligned.m8n8.x4.shared.b16 {%0,%1,%2,%3}, [%4];"
                 : "=r"(r[0]), "=r"(r[1]), "=r"(r[2]), "=r"(r[3]) : "r"(addr));
}
__device__ __forceinline__ void mma_bf16(float* c, const uint32_t* a, uint32_t b0, uint32_t b1) {
    asm volatile("mma.sync.aligned.m16n8k16.row.col.f32.bf16.bf16.f32 "
                 "{%0,%1,%2,%3}, {%4,%5,%6,%7}, {%8,%9}, {%0,%1,%2,%3};"
                 : "+f"(c[0]), "+f"(c[1]), "+f"(c[2]), "+f"(c[3])
                 : "r"(a[0]), "r"(a[1]), "r"(a[2]), "r"(a[3]), "r"(b0), "r"(b1));
}

// ---------------------------------------------------------------------------
// hi/lo bf16 split
// ---------------------------------------------------------------------------
__device__ __forceinline__ void split2(float v, unsigned short& h, unsigned short& l) {
    __nv_bfloat16 hb = __float2bfloat16_rn(v);
    __nv_bfloat16 lb = __float2bfloat16_rn(v - __bfloat162float(hb));
    h = __bfloat16_as_ushort(hb);
    l = __bfloat16_as_ushort(lb);
}

// ---------------------------------------------------------------------------
// Kernel 1: split X -> Ahi/Alo[:, 0:1024]
// ---------------------------------------------------------------------------
__global__ void __launch_bounds__(256)
convertX_kernel(const float* __restrict__ X)
{
    const int t = blockIdx.x * 256 + threadIdx.x;
    const int m = t >> 8;
    const int f = (t & 255) << 2;
    const float4 v = *reinterpret_cast<const float4*>(X + (size_t)m * F_DIM + f);
    ushort4 hv, lv;
    split2(v.x, hv.x, lv.x); split2(v.y, hv.y, lv.y);
    split2(v.z, hv.z, lv.z); split2(v.w, hv.w, lv.w);
    *reinterpret_cast<ushort4*>(&g_Ahi[(size_t)m * K_DIM + f]) = hv;
    *reinterpret_cast<ushort4*>(&g_Alo[(size_t)m * K_DIM + f]) = lv;
}

// ---------------------------------------------------------------------------
// Kernel 2: aggregate + split -> Ahi/Alo[:, 1024:2048]
// ---------------------------------------------------------------------------
__global__ void __launch_bounds__(256)
aggregate_kernel(const float* __restrict__ X, const int* __restrict__ idx)
{
    const int n  = blockIdx.x;
    const int f4 = threadIdx.x;
    const int* row_idx = idx + n * NUM_NEIGH;
    float4 acc = make_float4(0.f, 0.f, 0.f, 0.f);
#pragma unroll
    for (int j = 0; j < NUM_NEIGH; ++j) {
        const int nb = row_idx[j];
        const float4 v = *reinterpret_cast<const float4*>(X + (size_t)nb * F_DIM + f4 * 4);
        acc.x += v.x; acc.y += v.y; acc.z += v.z; acc.w += v.w;
    }
    const float s = 1.0f / NUM_NEIGH;
    acc.x *= s; acc.y *= s; acc.z *= s; acc.w *= s;
    ushort4 hv, lv;
    split2(acc.x, hv.x, lv.x); split2(acc.y, hv.y, lv.y);
    split2(acc.z, hv.z, lv.z); split2(acc.w, hv.w, lv.w);
    const size_t o = (size_t)n * K_DIM + F_DIM + f4 * 4;
    *reinterpret_cast<ushort4*>(&g_Ahi[o]) = hv;
    *reinterpret_cast<ushort4*>(&g_Alo[o]) = lv;
}

// ---------------------------------------------------------------------------
// Kernel 3: transpose + split W[2048,1024] -> Bhi/Blo[1024,2048] (K-major)
// ---------------------------------------------------------------------------
__global__ void __launch_bounds__(256)
convertW_kernel(const float* __restrict__ W)
{
    __shared__ float tile[32][33];
    const int n0 = blockIdx.x * 32;
    const int k0 = blockIdx.y * 32;
    const int tx = threadIdx.x & 31;
    const int ty = threadIdx.x >> 5;          // 0..7
    for (int i = ty; i < 32; i += 8)
        tile[i][tx] = W[(size_t)(k0 + i) * O_DIM + n0 + tx];
    __syncthreads();
    for (int i = ty; i < 32; i += 8) {
        const float v = tile[tx][i];          // W[k0+tx][n0+i]
        unsigned short h, l;
        split2(v, h, l);
        const size_t o = (size_t)(n0 + i) * K_DIM + k0 + tx;
        g_Bhi[o] = __ushort_as_bfloat16(h);
        g_Blo[o] = __ushort_as_bfloat16(l);
    }
}

// ---------------------------------------------------------------------------
// Kernel 4: mma.sync bf16 GEMM over K' = 3*2048
//   out = Ahi@Bhi' + Ahi@Blo' + Alo@Bhi' + bias
// CTA 128x128, 8 warps (4x2) each 32x64 -> 16 warps/SM at 2 CTAs/SM.
// BK=32, 4-stage cp.async multistage pipeline, 80B-padded smem rows
// (conflict-free LDSM + STS, no swizzle ALU in the hot loop).
// ---------------------------------------------------------------------------
__global__ void __launch_bounds__(NTHREADS, 2)
gemm_kernel(const float* __restrict__ bias, float* __restrict__ out)
{
    extern __shared__ char smem_raw[];
    const uint32_t smem = smem_u32(smem_raw);

    const int tid  = threadIdx.x;
    const int lane = tid & 31;
    const int wid  = tid >> 5;            // 0..7
    const int m0 = blockIdx.y * BM;
    const int n0 = blockIdx.x * BN;
    const int wm = (wid >> 1) * 32;       // warp row offset (0,32,64,96)
    const int wn = (wid & 1) * 64;        // warp col offset (0,64)

    const __nv_bfloat16* const Aseg[3] = { g_Ahi, g_Ahi, g_Alo };
    const __nv_bfloat16* const Bseg[3] = { g_Bhi, g_Blo, g_Bhi };

    // cp.async mapping: 256 threads; thread t -> row (t&127), 32B half (t>>7)
    const int srow = tid & 127;
    const int half = tid >> 7;            // 0 or 1

    auto load_stage = [&](int s, int it) {
        const int seg = it >> 6;                  // 0..2
        const int kk  = ((it & 63) << 5) + half * 16;   // k element offset
        const char* srcA = (const char*)(Aseg[seg] + (size_t)(m0 + srow) * K_DIM + kk);
        const char* srcB = (const char*)(Bseg[seg] + (size_t)(n0 + srow) * K_DIM + kk);
        const uint32_t dA = smem + s * STAGE_BYTES + srow * ROW_BYTES + half * 32;
        const uint32_t dB = dA + TILE_BYTES;
        cp_async16(dA,      srcA);
        cp_async16(dA + 16, srcA + 16);
        cp_async16(dB,      srcB);
        cp_async16(dB + 16, srcB + 16);
    };

    float acc[2][8][4];
#pragma unroll
    for (int i = 0; i < 2; ++i)
#pragma unroll
        for (int j = 0; j < 8; ++j)
#pragma unroll
            for (int v = 0; v < 4; ++v) acc[i][j][v] = 0.f;

    // prologue: fill STAGES-1 stages
#pragma unroll
    for (int s = 0; s < STAGES - 1; ++s) {
        load_stage(s, s);
        cp_commit();
    }

    // ldmatrix lane addressing (16 rows x 2 k-chunks per ldsm4)
    const int lrow = lane & 15;
    const int lkc  = lane >> 4;               // 0/1
    uint32_t aoff[2], boff[4];
#pragma unroll
    for (int t = 0; t < 2; ++t) aoff[t] = (wm + t * 16 + lrow) * ROW_BYTES;
#pragma unroll
    for (int t = 0; t < 4; ++t) boff[t] = (wn + t * 16 + lrow) * ROW_BYTES;

    for (int it = 0; it < CHUNKS; ++it) {
        cp_wait<STAGES - 2>();
        __syncthreads();

        if (it + STAGES - 1 < CHUNKS)
            load_stage((it + STAGES - 1) & (STAGES - 1), it + STAGES - 1);
        cp_commit();       // unconditional: keeps group count aligned

        const uint32_t sA = smem + (it & (STAGES - 1)) * STAGE_BYTES;
        const uint32_t sB = sA + TILE_BYTES;

#pragma unroll
        for (int k16 = 0; k16 < 2; ++k16) {
            uint32_t afr[2][4], bfr[4][4];
            const uint32_t kb = (uint32_t)(k16 * 2 + lkc) << 4;
#pragma unroll
            for (int tm = 0; tm < 2; ++tm)
                ldsm4(afr[tm], sA + aoff[tm] + kb);
#pragma unroll
            for (int tn2 = 0; tn2 < 4; ++tn2)
                ldsm4(bfr[tn2], sB + boff[tn2] + kb);
#pragma unroll
            for (int tm = 0; tm < 2; ++tm)
#pragma unroll
                for (int tn = 0; tn < 8; ++tn)
                    mma_bf16(acc[tm][tn], afr[tm],
                             bfr[tn >> 1][tn & 1], bfr[tn >> 1][(tn & 1) + 2]);
        }
    }

    // ---- epilogue: + bias, direct f32 stores (float2 per fragment row) ----
    const int qn = (lane & 3) * 2;   // n offset within n8 tile
    const int qm = lane >> 2;        // m offset within m16 tile (0..7)
    float2 b2[8];
#pragma unroll
    for (int tn = 0; tn < 8; ++tn) {
        const int n = n0 + wn + tn * 8 + qn;
        b2[tn] = *reinterpret_cast<const float2*>(bias + n);
    }
#pragma unroll
    for (int tm = 0; tm < 2; ++tm) {
        const int m = m0 + wm + tm * 16 + qm;
#pragma unroll
        for (int tn = 0; tn < 8; ++tn) {
            const int n = n0 + wn + tn * 8 + qn;
            float2 lo, hi;
            lo.x = acc[tm][tn][0] + b2[tn].x;
            lo.y = acc[tm][tn][1] + b2[tn].y;
            hi.x = acc[tm][tn][2] + b2[tn].x;
            hi.y = acc[tm][tn][3] + b2[tn].y;
            *reinterpret_cast<float2*>(out + (size_t)m * O_DIM + n)       = lo;
            *reinterpret_cast<float2*>(out + (size_t)(m + 8) * O_DIM + n) = hi;
        }
    }
}

// ---------------------------------------------------------------------------
// Launch: inputs in metadata order: X, A(unused), W, b, sampled_idx
// ---------------------------------------------------------------------------
extern "C" void kernel_launch(void* const* d_in, const int* in_sizes, int n_in,
                              void* d_out, int out_size)
{
    const float* X    = (const float*)d_in[0];
    const float* W    = (const float*)d_in[2];
    const float* bias = (const float*)d_in[3];
    const int*   idx  = (const int*)d_in[4];
    float* out = (float*)d_out;

    cudaFuncSetAttribute(gemm_kernel, cudaFuncAttributeMaxDynamicSharedMemorySize, SMEM_NEED);

    convertX_kernel<<<(N_NODES * F_DIM / 4) / 256, 256>>>(X);
    convertW_kernel<<<dim3(O_DIM / 32, K_DIM / 32), 256>>>(W);
    aggregate_kernel<<<N_NODES, 256>>>(X, idx);

    dim3 grid(O_DIM / BN, N_NODES / BM);   // (8, 64) = 512 CTAs
    gemm_kernel<<<grid, NTHREADS, SMEM_NEED>>>(bias, out);
    (void)in_sizes; (void)n_in; (void)out_size;
}